// round 13
// baseline (speedup 1.0000x reference)
#include <cuda_runtime.h>
#include <cuda_fp16.h>

#define N_NODES  100000
#define N_EDGES  3200000
#define N_GRAPHS 128
#define CAP      128            // fixed CSR capacity per node (max deg ~66 here)
#define LOG2CAP  7

// ---------------- scratch (device globals: no allocations allowed) ----------
__device__ __half g_h1[N_NODES * 64];    // x@W1, UNscaled fp16
__device__ __half g_h2[N_NODES * 32];    // layer-2 features (dinv-scaled), fp16
__device__ float  g_dinv[N_NODES];
__device__ int    g_cursor[N_NODES];     // per-node fill cursor == in-degree
__device__ int    g_csr[N_NODES * CAP];  // src node per slot (fixed capacity)
__device__ float  g_pool[N_GRAPHS * 32];

union HU4 { uint4 u; __half2 h[4]; };

// ---------------- fixed-capacity CSR build ----------------------------------
__global__ void cur_init_kernel() {
    int i = blockIdx.x * blockDim.x + threadIdx.x;
    if (i < N_NODES) g_cursor[i] = 0;
}

__global__ void csr_fill_kernel(const int* __restrict__ ei) {
    int e = blockIdx.x * blockDim.x + threadIdx.x;
    if (e < N_EDGES) {
        int src = __ldg(ei + e);
        int dst = __ldg(ei + N_EDGES + e);
        int p = atomicAdd(&g_cursor[dst], 1);
        if (p < CAP) g_csr[((size_t)dst << LOG2CAP) + p] = src;
    }
}

__global__ void dinv_kernel() {
    int i = blockIdx.x * blockDim.x + threadIdx.x;
    if (i < N_NODES) g_dinv[i] = rsqrtf((float)(g_cursor[i] + 1));
}

// ---------------- GEMM 1: h1 = fp16(x @ W1)  (UNscaled — independent) -------
__global__ void __launch_bounds__(256) xw1_kernel(const float* __restrict__ x,
                                                  const float* __restrict__ W1) {
    __shared__ float sW[47 * 64];       // 12 KB
    __shared__ float sx[128 * 47];      // 23.5 KB
    int tid = threadIdx.x;
    for (int i = tid; i < 47 * 64; i += 256) sW[i] = W1[i];
    int row0 = blockIdx.x * 128;
    int nrow = min(128, N_NODES - row0);
    for (int i = tid; i < nrow * 47; i += 256) sx[i] = x[(size_t)row0 * 47 + i];
    __syncthreads();

    int rg = tid >> 3;                  // 0..31 (row group of 4)
    int cg = (tid & 7) * 8;             // 8 output cols
    const float* xb = sx + rg * 4 * 47;

    float acc[4][8];
#pragma unroll
    for (int rr = 0; rr < 4; rr++)
#pragma unroll
        for (int j = 0; j < 8; j++) acc[rr][j] = 0.f;

#pragma unroll 4
    for (int k = 0; k < 47; k++) {
        float4 w0 = *(const float4*)&sW[k * 64 + cg];
        float4 w1 = *(const float4*)&sW[k * 64 + cg + 4];
#pragma unroll
        for (int rr = 0; rr < 4; rr++) {
            float xv = xb[rr * 47 + k];
            acc[rr][0] += xv * w0.x; acc[rr][1] += xv * w0.y;
            acc[rr][2] += xv * w0.z; acc[rr][3] += xv * w0.w;
            acc[rr][4] += xv * w1.x; acc[rr][5] += xv * w1.y;
            acc[rr][6] += xv * w1.z; acc[rr][7] += xv * w1.w;
        }
    }
#pragma unroll
    for (int rr = 0; rr < 4; rr++) {
        int row = row0 + rg * 4 + rr;
        if (row < N_NODES) {
            HU4 o;
            o.h[0] = __float22half2_rn(make_float2(acc[rr][0], acc[rr][1]));
            o.h[1] = __float22half2_rn(make_float2(acc[rr][2], acc[rr][3]));
            o.h[2] = __float22half2_rn(make_float2(acc[rr][4], acc[rr][5]));
            o.h[3] = __float22half2_rn(make_float2(acc[rr][6], acc[rr][7]));
            *(uint4*)(g_h1 + (size_t)row * 64 + cg) = o.u;
        }
    }
}

// ---------------- helpers ----------------------------------------------------
// acc += v (plain)
__device__ __forceinline__ void acc8(float2& a0, float2& a1, float2& a2, float2& a3,
                                     const HU4& v) {
    float2 f;
    f = __half22float2(v.h[0]); a0.x += f.x; a0.y += f.y;
    f = __half22float2(v.h[1]); a1.x += f.x; a1.y += f.y;
    f = __half22float2(v.h[2]); a2.x += f.x; a2.y += f.y;
    f = __half22float2(v.h[3]); a3.x += f.x; a3.y += f.y;
}
// acc += v * s (FMA)
__device__ __forceinline__ void acc8s(float2& a0, float2& a1, float2& a2, float2& a3,
                                      const HU4& v, float s) {
    float2 f;
    f = __half22float2(v.h[0]); a0.x += f.x * s; a0.y += f.y * s;
    f = __half22float2(v.h[1]); a1.x += f.x * s; a1.y += f.y * s;
    f = __half22float2(v.h[2]); a2.x += f.x * s; a2.y += f.y * s;
    f = __half22float2(v.h[3]); a3.x += f.x * s; a3.y += f.y * s;
}

// ---------------- FUSED: gather layer1 (per-edge dinv) + bias/relu + @W2 ----
// h1 unscaled: out = dd*(sum_src dinv[src]*h1[src] + dd*h1[self]); 8 lanes/node.
__global__ void __launch_bounds__(256) gather1_xw2_kernel(const float* __restrict__ W2,
                                                          const float* __restrict__ b1) {
    __shared__ float sW[64 * 32];       // 8 KB, row-major [k][out]
    __shared__ float sb[64];
    __shared__ float sR[32 * 68];       // 32 nodes x 64 feats, stride 68 (8.5 KB)
    {
        int tid = threadIdx.x;
        for (int i = tid; i < 64 * 32; i += 256) sW[i] = W2[i];
        if (tid < 64) sb[tid] = b1[tid];
    }
    __syncthreads();

    unsigned t = blockIdx.x * blockDim.x + threadIdx.x;
    unsigned node = t >> 3;
    unsigned grp = t & 7;               // lane within node group
    unsigned nl  = threadIdx.x >> 3;    // node-local index 0..31

    int cnt = min(__ldg(&g_cursor[node]), CAP);
    float dd = rsqrtf((float)(cnt + 1));
    const int* row = g_csr + ((size_t)node << LOG2CAP);
    const uint4* H = (const uint4*)g_h1;
    unsigned base = (node << 3) + grp;

    // accumulators init with dd * h1[self]
    HU4 self; self.u = __ldg(&H[base]);
    float2 a0, a1, a2, a3;
    {
        float2 f;
        f = __half22float2(self.h[0]); a0 = make_float2(f.x * dd, f.y * dd);
        f = __half22float2(self.h[1]); a1 = make_float2(f.x * dd, f.y * dd);
        f = __half22float2(self.h[2]); a2 = make_float2(f.x * dd, f.y * dd);
        f = __half22float2(self.h[3]); a3 = make_float2(f.x * dd, f.y * dd);
    }
    float2 b0 = make_float2(0.f, 0.f), b1v = make_float2(0.f, 0.f);
    float2 b2 = make_float2(0.f, 0.f), b3 = make_float2(0.f, 0.f);

    int j = 0;
    for (; j + 3 < cnt; j += 4) {
        int i0 = __ldg(row + j);
        int i1 = __ldg(row + j + 1);
        int i2 = __ldg(row + j + 2);
        int i3 = __ldg(row + j + 3);
        float d0 = __ldg(&g_dinv[i0]);
        float d1 = __ldg(&g_dinv[i1]);
        float d2 = __ldg(&g_dinv[i2]);
        float d3 = __ldg(&g_dinv[i3]);
        HU4 v0; v0.u = __ldg(&H[((size_t)i0 << 3) + grp]);
        HU4 v1; v1.u = __ldg(&H[((size_t)i1 << 3) + grp]);
        HU4 v2; v2.u = __ldg(&H[((size_t)i2 << 3) + grp]);
        HU4 v3; v3.u = __ldg(&H[((size_t)i3 << 3) + grp]);
        acc8s(a0, a1, a2, a3, v0, d0);
        acc8s(b0, b1v, b2, b3, v1, d1);
        acc8s(a0, a1, a2, a3, v2, d2);
        acc8s(b0, b1v, b2, b3, v3, d3);
    }
    for (; j < cnt; j++) {
        int i0 = __ldg(row + j);
        float d0 = __ldg(&g_dinv[i0]);
        HU4 v0; v0.u = __ldg(&H[((size_t)i0 << 3) + grp]);
        acc8s(a0, a1, a2, a3, v0, d0);
    }

    // r = relu(acc * dd + b1) -> shared
    float* rdst = &sR[nl * 68 + grp * 8];
    rdst[0] = fmaxf((a0.x + b0.x) * dd + sb[grp * 8 + 0], 0.f);
    rdst[1] = fmaxf((a0.y + b0.y) * dd + sb[grp * 8 + 1], 0.f);
    rdst[2] = fmaxf((a1.x + b1v.x) * dd + sb[grp * 8 + 2], 0.f);
    rdst[3] = fmaxf((a1.y + b1v.y) * dd + sb[grp * 8 + 3], 0.f);
    rdst[4] = fmaxf((a2.x + b2.x) * dd + sb[grp * 8 + 4], 0.f);
    rdst[5] = fmaxf((a2.y + b2.y) * dd + sb[grp * 8 + 5], 0.f);
    rdst[6] = fmaxf((a3.x + b3.x) * dd + sb[grp * 8 + 6], 0.f);
    rdst[7] = fmaxf((a3.y + b3.y) * dd + sb[grp * 8 + 7], 0.f);
    __syncwarp();   // node's 8 lanes are in this warp

    // this lane's 4 h2 outputs: acc4[o] = sum_k r[k] * W2[k][grp*4+o]
    const float* rsrc = &sR[nl * 68];
    float4 acc4 = make_float4(0.f, 0.f, 0.f, 0.f);
#pragma unroll 8
    for (int k = 0; k < 64; k++) {
        float h = rsrc[k];
        float4 w = *(const float4*)&sW[k * 32 + grp * 4];
        acc4.x += h * w.x; acc4.y += h * w.y;
        acc4.z += h * w.z; acc4.w += h * w.w;
    }

    // h2 = fp16(acc4 * dd)  (row-dinv pre-applied for layer 2)
    __half2 p0 = __float22half2_rn(make_float2(acc4.x * dd, acc4.y * dd));
    __half2 p1 = __float22half2_rn(make_float2(acc4.z * dd, acc4.w * dd));
    uint2 u = make_uint2(*(unsigned*)&p0, *(unsigned*)&p1);
    *(uint2*)(g_h2 + (size_t)node * 32 + grp * 4) = u;
}

// ---------------- FUSED: gather layer2 + bias/relu + block-smem pool --------
// 4 lanes/node, 64 nodes/block. Accumulate relu(out+b2) into a block-local
// smem pool table, flush only the touched graph rows with global atomics.
__global__ void __launch_bounds__(256) gather2_pool_kernel(const int* __restrict__ batch,
                                                           const float* __restrict__ b2v) {
    __shared__ float sP[N_GRAPHS * 32];    // 16 KB
    int tid = threadIdx.x;

    // block's node range -> graph range (batch sorted)
    unsigned n0 = blockIdx.x * 64u;
    unsigned nlast = min(n0 + 63u, (unsigned)(N_NODES - 1));
    int g0 = __ldg(&batch[n0]);
    int g1 = __ldg(&batch[nlast]);
    int nflush = (g1 - g0 + 1) * 32;
    for (int i = tid; i < nflush; i += 256) sP[g0 * 32 + i] = 0.f;
    __syncthreads();

    unsigned t = blockIdx.x * 256u + tid;
    unsigned node = t >> 2;
    unsigned lane = t & 3;

    if (node < N_NODES) {
        int cnt = min(__ldg(&g_cursor[node]), CAP);
        float dd = rsqrtf((float)(cnt + 1));
        const int* row = g_csr + ((size_t)node << LOG2CAP);
        const uint4* H = (const uint4*)g_h2;
        unsigned base = (node << 2) + lane;

        HU4 self; self.u = __ldg(&H[base]);
        float2 a0 = __half22float2(self.h[0]);
        float2 a1 = __half22float2(self.h[1]);
        float2 a2 = __half22float2(self.h[2]);
        float2 a3 = __half22float2(self.h[3]);
        float2 b0 = make_float2(0.f, 0.f), b1 = make_float2(0.f, 0.f);
        float2 b2 = make_float2(0.f, 0.f), b3 = make_float2(0.f, 0.f);

        int j = 0;
        for (; j + 3 < cnt; j += 4) {
            int i0 = __ldg(row + j);
            int i1 = __ldg(row + j + 1);
            int i2 = __ldg(row + j + 2);
            int i3 = __ldg(row + j + 3);
            HU4 v0; v0.u = __ldg(&H[((size_t)i0 << 2) + lane]);
            HU4 v1; v1.u = __ldg(&H[((size_t)i1 << 2) + lane]);
            HU4 v2; v2.u = __ldg(&H[((size_t)i2 << 2) + lane]);
            HU4 v3; v3.u = __ldg(&H[((size_t)i3 << 2) + lane]);
            acc8(a0, a1, a2, a3, v0);
            acc8(b0, b1, b2, b3, v1);
            acc8(a0, a1, a2, a3, v2);
            acc8(b0, b1, b2, b3, v3);
        }
        for (; j < cnt; j++) {
            int i0 = __ldg(row + j);
            HU4 v0; v0.u = __ldg(&H[((size_t)i0 << 2) + lane]);
            acc8(a0, a1, a2, a3, v0);
        }

        float v[8];
        v[0] = (a0.x + b0.x) * dd; v[1] = (a0.y + b0.y) * dd;
        v[2] = (a1.x + b1.x) * dd; v[3] = (a1.y + b1.y) * dd;
        v[4] = (a2.x + b2.x) * dd; v[5] = (a2.y + b2.y) * dd;
        v[6] = (a3.x + b3.x) * dd; v[7] = (a3.y + b3.y) * dd;

        int g = __ldg(&batch[node]);
        float* prow = &sP[g * 32 + lane * 8];
        const float4 bb0 = __ldg((const float4*)(b2v + lane * 8));
        const float4 bb1 = __ldg((const float4*)(b2v + lane * 8 + 4));
        atomicAdd(&prow[0], fmaxf(v[0] + bb0.x, 0.f));
        atomicAdd(&prow[1], fmaxf(v[1] + bb0.y, 0.f));
        atomicAdd(&prow[2], fmaxf(v[2] + bb0.z, 0.f));
        atomicAdd(&prow[3], fmaxf(v[3] + bb0.w, 0.f));
        atomicAdd(&prow[4], fmaxf(v[4] + bb1.x, 0.f));
        atomicAdd(&prow[5], fmaxf(v[5] + bb1.y, 0.f));
        atomicAdd(&prow[6], fmaxf(v[6] + bb1.z, 0.f));
        atomicAdd(&prow[7], fmaxf(v[7] + bb1.w, 0.f));
    }
    __syncthreads();

    // flush touched graph rows to global pool
    for (int i = tid; i < nflush; i += 256) {
        float val = sP[g0 * 32 + i];
        if (val != 0.f) atomicAdd(&g_pool[g0 * 32 + i], val);
    }
}

// ---------------- pooling buffer zero ----------------------------------------
__global__ void pool_zero_kernel() {
    int i = blockIdx.x * blockDim.x + threadIdx.x;
    if (i < N_GRAPHS * 32) g_pool[i] = 0.f;
}

// ---------------- tiny MLP head: [128,32] -> [128,1] ------------------------
__global__ void mlp_kernel(const float* __restrict__ A1, const float* __restrict__ c1,
                           const float* __restrict__ A2, const float* __restrict__ c2,
                           const float* __restrict__ A3, const float* __restrict__ c3,
                           const float* __restrict__ A4, const float* __restrict__ c4,
                           float* __restrict__ out) {
    __shared__ float sA1[32 * 32], sA2[32 * 16], sA3[16 * 8], sA4[8];
    __shared__ float sc1[32], sc2[16], sc3[8];
    int tid = threadIdx.x;  // 128 threads, one per graph
    for (int i = tid; i < 1024; i += 128) sA1[i] = A1[i];
    for (int i = tid; i < 512;  i += 128) sA2[i] = A2[i];
    if (tid < 128) sA3[tid] = A3[tid];
    if (tid < 8)  sA4[tid] = A4[tid];
    if (tid < 32) sc1[tid] = c1[tid];
    if (tid < 16) sc2[tid] = c2[tid];
    if (tid < 8)  sc3[tid] = c3[tid];
    __syncthreads();

    float g[32];
#pragma unroll
    for (int i = 0; i < 32; i++) g[i] = g_pool[tid * 32 + i];

    float v1[32];
#pragma unroll
    for (int o = 0; o < 32; o++) {
        float a = sc1[o];
#pragma unroll
        for (int k = 0; k < 32; k++) a += g[k] * sA1[k * 32 + o];
        v1[o] = fmaxf(a, 0.f);
    }
    float v2[16];
#pragma unroll
    for (int o = 0; o < 16; o++) {
        float a = sc2[o];
#pragma unroll
        for (int k = 0; k < 32; k++) a += v1[k] * sA2[k * 16 + o];
        v2[o] = fmaxf(a, 0.f);
    }
    float v3[8];
#pragma unroll
    for (int o = 0; o < 8; o++) {
        float a = sc3[o];
#pragma unroll
        for (int k = 0; k < 16; k++) a += v2[k] * sA3[k * 8 + o];
        v3[o] = fmaxf(a, 0.f);
    }
    float r = __ldg(c4);
#pragma unroll
    for (int k = 0; k < 8; k++) r += v3[k] * sA4[k];
    out[tid] = r;
}

// ---------------- launch: xw1 on side stream overlaps CSR build --------------
extern "C" void kernel_launch(void* const* d_in, const int* in_sizes, int n_in,
                              void* d_out, int out_size) {
    const float* x     = (const float*)d_in[0];
    const int*   ei    = (const int*)  d_in[1];
    const int*   batch = (const int*)  d_in[2];
    const float* W1 = (const float*)d_in[3];  const float* b1 = (const float*)d_in[4];
    const float* W2 = (const float*)d_in[5];  const float* b2 = (const float*)d_in[6];
    const float* A1 = (const float*)d_in[7];  const float* c1 = (const float*)d_in[8];
    const float* A2 = (const float*)d_in[9];  const float* c2 = (const float*)d_in[10];
    const float* A3 = (const float*)d_in[11]; const float* c3 = (const float*)d_in[12];
    const float* A4 = (const float*)d_in[13]; const float* c4 = (const float*)d_in[14];
    float* out = (float*)d_out;

    // side stream + fork/join events (created once, outside capture)
    static cudaStream_t s2 = [] {
        cudaStream_t s; cudaStreamCreateWithFlags(&s, cudaStreamNonBlocking); return s;
    }();
    static cudaEvent_t evF = [] {
        cudaEvent_t e; cudaEventCreateWithFlags(&e, cudaEventDisableTiming); return e;
    }();
    static cudaEvent_t evJ = [] {
        cudaEvent_t e; cudaEventCreateWithFlags(&e, cudaEventDisableTiming); return e;
    }();

    // fork: xw1 is fully independent
    cudaEventRecord(evF, 0);
    cudaStreamWaitEvent(s2, evF, 0);
    xw1_kernel<<<(N_NODES + 127) / 128, 256, 0, s2>>>(x, W1);             // idx 0

    // main: CSR build + dinv + pool zero, overlapping xw1
    cur_init_kernel<<<(N_NODES + 255) / 256, 256>>>();                    // idx 1
    csr_fill_kernel<<<(N_EDGES + 255) / 256, 256>>>(ei);                  // idx 2
    dinv_kernel<<<(N_NODES + 255) / 256, 256>>>();                        // idx 3
    pool_zero_kernel<<<(N_GRAPHS * 32 + 255) / 256, 256>>>();

    // join: gather1_xw2 needs CSR+dinv (main) and h1 (s2)
    cudaEventRecord(evJ, s2);
    cudaStreamWaitEvent(0, evJ, 0);

    gather1_xw2_kernel<<<N_NODES * 8 / 256, 256>>>(W2, b1);               // fused L1+W2
    gather2_pool_kernel<<<(N_NODES * 4 + 255) / 256, 256>>>(batch, b2);   // fused L2+pool
    mlp_kernel<<<1, 128>>>(A1, c1, A2, c2, A3, c3, A4, c4, out);
}

// round 14
// speedup vs baseline: 1.0442x; 1.0442x over previous
#include <cuda_runtime.h>
#include <cuda_fp16.h>

#define N_NODES  100000
#define N_EDGES  3200000
#define N_GRAPHS 128
#define CAP      128            // fixed CSR capacity per node (max deg ~66 here)
#define LOG2CAP  7

// ---------------- scratch (device globals: no allocations allowed) ----------
__device__ __half g_h1[N_NODES * 64];    // x@W1 (unscaled), then scaled in place
__device__ __half g_h2[N_NODES * 32];    // layer-2 features (dinv-scaled), fp16
__device__ float  g_dinv[N_NODES];
__device__ int    g_cursor[N_NODES];     // per-node fill cursor == in-degree
__device__ int    g_csr[N_NODES * CAP];  // src node per slot (fixed capacity)
__device__ float  g_pool[N_GRAPHS * 32];

union HU4 { uint4 u; __half2 h[4]; };

// ---------------- fixed-capacity CSR build ----------------------------------
__global__ void cur_init_kernel() {
    int i = blockIdx.x * blockDim.x + threadIdx.x;
    if (i < N_NODES) g_cursor[i] = 0;
}

__global__ void csr_fill_kernel(const int* __restrict__ ei) {
    int e = blockIdx.x * blockDim.x + threadIdx.x;
    if (e < N_EDGES) {
        int src = __ldg(ei + e);
        int dst = __ldg(ei + N_EDGES + e);
        int p = atomicAdd(&g_cursor[dst], 1);
        if (p < CAP) g_csr[((size_t)dst << LOG2CAP) + p] = src;
    }
}

// ---------------- scale pass: g_dinv + h1 *= dinv[row] (in place) -----------
__global__ void __launch_bounds__(256) scale1_kernel() {
    unsigned t = blockIdx.x * blockDim.x + threadIdx.x;
    if (t >= (unsigned)N_NODES * 8) return;
    unsigned node = t >> 3;
    unsigned lane = t & 7;
    float d = rsqrtf((float)(__ldg(&g_cursor[node]) + 1));
    if (lane == 0) g_dinv[node] = d;
    uint4* p = (uint4*)g_h1 + ((size_t)node << 3) + lane;
    HU4 v; v.u = *p;
#pragma unroll
    for (int i = 0; i < 4; i++) {
        float2 f = __half22float2(v.h[i]);
        v.h[i] = __float22half2_rn(make_float2(f.x * d, f.y * d));
    }
    *p = v.u;
}

// ---------------- GEMM 1: h1 = fp16(x @ W1)  (UNscaled — independent) -------
__global__ void __launch_bounds__(256) xw1_kernel(const float* __restrict__ x,
                                                  const float* __restrict__ W1) {
    __shared__ float sW[47 * 64];       // 12 KB
    __shared__ float sx[128 * 47];      // 23.5 KB
    int tid = threadIdx.x;
    for (int i = tid; i < 47 * 64; i += 256) sW[i] = W1[i];
    int row0 = blockIdx.x * 128;
    int nrow = min(128, N_NODES - row0);
    for (int i = tid; i < nrow * 47; i += 256) sx[i] = x[(size_t)row0 * 47 + i];
    __syncthreads();

    int rg = tid >> 3;                  // 0..31 (row group of 4)
    int cg = (tid & 7) * 8;             // 8 output cols
    const float* xb = sx + rg * 4 * 47;

    float acc[4][8];
#pragma unroll
    for (int rr = 0; rr < 4; rr++)
#pragma unroll
        for (int j = 0; j < 8; j++) acc[rr][j] = 0.f;

#pragma unroll 4
    for (int k = 0; k < 47; k++) {
        float4 w0 = *(const float4*)&sW[k * 64 + cg];
        float4 w1 = *(const float4*)&sW[k * 64 + cg + 4];
#pragma unroll
        for (int rr = 0; rr < 4; rr++) {
            float xv = xb[rr * 47 + k];
            acc[rr][0] += xv * w0.x; acc[rr][1] += xv * w0.y;
            acc[rr][2] += xv * w0.z; acc[rr][3] += xv * w0.w;
            acc[rr][4] += xv * w1.x; acc[rr][5] += xv * w1.y;
            acc[rr][6] += xv * w1.z; acc[rr][7] += xv * w1.w;
        }
    }
#pragma unroll
    for (int rr = 0; rr < 4; rr++) {
        int row = row0 + rg * 4 + rr;
        if (row < N_NODES) {
            HU4 o;
            o.h[0] = __float22half2_rn(make_float2(acc[rr][0], acc[rr][1]));
            o.h[1] = __float22half2_rn(make_float2(acc[rr][2], acc[rr][3]));
            o.h[2] = __float22half2_rn(make_float2(acc[rr][4], acc[rr][5]));
            o.h[3] = __float22half2_rn(make_float2(acc[rr][6], acc[rr][7]));
            *(uint4*)(g_h1 + (size_t)row * 64 + cg) = o.u;
        }
    }
}

// ---------------- helpers ----------------------------------------------------
__device__ __forceinline__ void acc8(float2& a0, float2& a1, float2& a2, float2& a3,
                                     const HU4& v) {
    float2 f;
    f = __half22float2(v.h[0]); a0.x += f.x; a0.y += f.y;
    f = __half22float2(v.h[1]); a1.x += f.x; a1.y += f.y;
    f = __half22float2(v.h[2]); a2.x += f.x; a2.y += f.y;
    f = __half22float2(v.h[3]); a3.x += f.x; a3.y += f.y;
}

// ---------------- FUSED: gather layer1 + bias/relu + @W2 + store h2 ---------
// h1 pre-scaled; shared-memory transpose. 8 lanes/node, 32 nodes/block.
__global__ void __launch_bounds__(256) gather1_xw2_kernel(const float* __restrict__ W2,
                                                          const float* __restrict__ b1) {
    __shared__ float sW[64 * 32];       // 8 KB, row-major [k][out]
    __shared__ float sb[64];
    __shared__ float sR[32 * 68];       // 32 nodes x 64 feats, stride 68 (8.5 KB)
    {
        int tid = threadIdx.x;
        for (int i = tid; i < 64 * 32; i += 256) sW[i] = W2[i];
        if (tid < 64) sb[tid] = b1[tid];
    }
    __syncthreads();

    unsigned t = blockIdx.x * blockDim.x + threadIdx.x;
    unsigned node = t >> 3;
    unsigned grp = t & 7;               // lane within node group
    unsigned nl  = threadIdx.x >> 3;    // node-local index 0..31

    int cnt = min(__ldg(&g_cursor[node]), CAP);
    const int* row = g_csr + ((size_t)node << LOG2CAP);
    const uint4* H = (const uint4*)g_h1;
    unsigned base = (node << 3) + grp;

    HU4 self; self.u = __ldg(&H[base]);
    float2 a0 = __half22float2(self.h[0]);
    float2 a1 = __half22float2(self.h[1]);
    float2 a2 = __half22float2(self.h[2]);
    float2 a3 = __half22float2(self.h[3]);
    float2 b0 = make_float2(0.f, 0.f), b1v = make_float2(0.f, 0.f);
    float2 b2 = make_float2(0.f, 0.f), b3 = make_float2(0.f, 0.f);

    int j = 0;
    for (; j + 3 < cnt; j += 4) {
        int i0 = __ldg(row + j);
        int i1 = __ldg(row + j + 1);
        int i2 = __ldg(row + j + 2);
        int i3 = __ldg(row + j + 3);
        HU4 v0; v0.u = __ldg(&H[((size_t)i0 << 3) + grp]);
        HU4 v1; v1.u = __ldg(&H[((size_t)i1 << 3) + grp]);
        HU4 v2; v2.u = __ldg(&H[((size_t)i2 << 3) + grp]);
        HU4 v3; v3.u = __ldg(&H[((size_t)i3 << 3) + grp]);
        acc8(a0, a1, a2, a3, v0);
        acc8(b0, b1v, b2, b3, v1);
        acc8(a0, a1, a2, a3, v2);
        acc8(b0, b1v, b2, b3, v3);
    }
    for (; j < cnt; j++) {
        int i0 = __ldg(row + j);
        HU4 v0; v0.u = __ldg(&H[((size_t)i0 << 3) + grp]);
        acc8(a0, a1, a2, a3, v0);
    }

    float dd = g_dinv[node];
    // relu(agg*dinv + b1) -> shared (this lane's 8 layer-1 features)
    float* rdst = &sR[nl * 68 + grp * 8];
    rdst[0] = fmaxf((a0.x + b0.x) * dd + sb[grp * 8 + 0], 0.f);
    rdst[1] = fmaxf((a0.y + b0.y) * dd + sb[grp * 8 + 1], 0.f);
    rdst[2] = fmaxf((a1.x + b1v.x) * dd + sb[grp * 8 + 2], 0.f);
    rdst[3] = fmaxf((a1.y + b1v.y) * dd + sb[grp * 8 + 3], 0.f);
    rdst[4] = fmaxf((a2.x + b2.x) * dd + sb[grp * 8 + 4], 0.f);
    rdst[5] = fmaxf((a2.y + b2.y) * dd + sb[grp * 8 + 5], 0.f);
    rdst[6] = fmaxf((a3.x + b3.x) * dd + sb[grp * 8 + 6], 0.f);
    rdst[7] = fmaxf((a3.y + b3.y) * dd + sb[grp * 8 + 7], 0.f);
    __syncwarp();   // node's 8 lanes are in this warp

    // this lane's 4 h2 outputs: acc4[o] = sum_k r[k] * W2[k][grp*4+o]
    const float* rsrc = &sR[nl * 68];
    float4 acc4 = make_float4(0.f, 0.f, 0.f, 0.f);
#pragma unroll 8
    for (int k = 0; k < 64; k++) {
        float h = rsrc[k];
        float4 w = *(const float4*)&sW[k * 32 + grp * 4];
        acc4.x += h * w.x; acc4.y += h * w.y;
        acc4.z += h * w.z; acc4.w += h * w.w;
    }

    __half2 p0 = __float22half2_rn(make_float2(acc4.x * dd, acc4.y * dd));
    __half2 p1 = __float22half2_rn(make_float2(acc4.z * dd, acc4.w * dd));
    uint2 u = make_uint2(*(unsigned*)&p0, *(unsigned*)&p1);
    *(uint2*)(g_h2 + (size_t)node * 32 + grp * 4) = u;
}

// ---------------- FUSED: gather layer2 + bias/relu + block-smem pool --------
__global__ void __launch_bounds__(256) gather2_pool_kernel(const int* __restrict__ batch,
                                                           const float* __restrict__ b2v) {
    __shared__ float sP[N_GRAPHS * 32];    // 16 KB
    int tid = threadIdx.x;

    // block's node range -> graph range (batch sorted)
    unsigned n0 = blockIdx.x * 64u;
    unsigned nlast = min(n0 + 63u, (unsigned)(N_NODES - 1));
    int g0 = __ldg(&batch[n0]);
    int g1 = __ldg(&batch[nlast]);
    int nflush = (g1 - g0 + 1) * 32;
    for (int i = tid; i < nflush; i += 256) sP[g0 * 32 + i] = 0.f;
    __syncthreads();

    unsigned t = blockIdx.x * 256u + tid;
    unsigned node = t >> 2;
    unsigned lane = t & 3;

    if (node < N_NODES) {
        int cnt = min(__ldg(&g_cursor[node]), CAP);
        float dd = rsqrtf((float)(cnt + 1));
        const int* row = g_csr + ((size_t)node << LOG2CAP);
        const uint4* H = (const uint4*)g_h2;
        unsigned base = (node << 2) + lane;

        HU4 self; self.u = __ldg(&H[base]);
        float2 a0 = __half22float2(self.h[0]);
        float2 a1 = __half22float2(self.h[1]);
        float2 a2 = __half22float2(self.h[2]);
        float2 a3 = __half22float2(self.h[3]);
        float2 b0 = make_float2(0.f, 0.f), b1 = make_float2(0.f, 0.f);
        float2 b2 = make_float2(0.f, 0.f), b3 = make_float2(0.f, 0.f);

        int j = 0;
        for (; j + 3 < cnt; j += 4) {
            int i0 = __ldg(row + j);
            int i1 = __ldg(row + j + 1);
            int i2 = __ldg(row + j + 2);
            int i3 = __ldg(row + j + 3);
            HU4 v0; v0.u = __ldg(&H[((size_t)i0 << 2) + lane]);
            HU4 v1; v1.u = __ldg(&H[((size_t)i1 << 2) + lane]);
            HU4 v2; v2.u = __ldg(&H[((size_t)i2 << 2) + lane]);
            HU4 v3; v3.u = __ldg(&H[((size_t)i3 << 2) + lane]);
            acc8(a0, a1, a2, a3, v0);
            acc8(b0, b1, b2, b3, v1);
            acc8(a0, a1, a2, a3, v2);
            acc8(b0, b1, b2, b3, v3);
        }
        for (; j < cnt; j++) {
            int i0 = __ldg(row + j);
            HU4 v0; v0.u = __ldg(&H[((size_t)i0 << 2) + lane]);
            acc8(a0, a1, a2, a3, v0);
        }

        float v[8];
        v[0] = (a0.x + b0.x) * dd; v[1] = (a0.y + b0.y) * dd;
        v[2] = (a1.x + b1.x) * dd; v[3] = (a1.y + b1.y) * dd;
        v[4] = (a2.x + b2.x) * dd; v[5] = (a2.y + b2.y) * dd;
        v[6] = (a3.x + b3.x) * dd; v[7] = (a3.y + b3.y) * dd;

        int g = __ldg(&batch[node]);
        float* prow = &sP[g * 32 + lane * 8];
        const float4 bb0 = __ldg((const float4*)(b2v + lane * 8));
        const float4 bb1 = __ldg((const float4*)(b2v + lane * 8 + 4));
        atomicAdd(&prow[0], fmaxf(v[0] + bb0.x, 0.f));
        atomicAdd(&prow[1], fmaxf(v[1] + bb0.y, 0.f));
        atomicAdd(&prow[2], fmaxf(v[2] + bb0.z, 0.f));
        atomicAdd(&prow[3], fmaxf(v[3] + bb0.w, 0.f));
        atomicAdd(&prow[4], fmaxf(v[4] + bb1.x, 0.f));
        atomicAdd(&prow[5], fmaxf(v[5] + bb1.y, 0.f));
        atomicAdd(&prow[6], fmaxf(v[6] + bb1.z, 0.f));
        atomicAdd(&prow[7], fmaxf(v[7] + bb1.w, 0.f));
    }
    __syncthreads();

    // flush touched graph rows to global pool
    for (int i = tid; i < nflush; i += 256) {
        float val = sP[g0 * 32 + i];
        if (val != 0.f) atomicAdd(&g_pool[g0 * 32 + i], val);
    }
}

// ---------------- pooling buffer zero ----------------------------------------
__global__ void pool_zero_kernel() {
    int i = blockIdx.x * blockDim.x + threadIdx.x;
    if (i < N_GRAPHS * 32) g_pool[i] = 0.f;
}

// ---------------- tiny MLP head: [128,32] -> [128,1] ------------------------
__global__ void mlp_kernel(const float* __restrict__ A1, const float* __restrict__ c1,
                           const float* __restrict__ A2, const float* __restrict__ c2,
                           const float* __restrict__ A3, const float* __restrict__ c3,
                           const float* __restrict__ A4, const float* __restrict__ c4,
                           float* __restrict__ out) {
    __shared__ float sA1[32 * 32], sA2[32 * 16], sA3[16 * 8], sA4[8];
    __shared__ float sc1[32], sc2[16], sc3[8];
    int tid = threadIdx.x;  // 128 threads, one per graph
    for (int i = tid; i < 1024; i += 128) sA1[i] = A1[i];
    for (int i = tid; i < 512;  i += 128) sA2[i] = A2[i];
    if (tid < 128) sA3[tid] = A3[tid];
    if (tid < 8)  sA4[tid] = A4[tid];
    if (tid < 32) sc1[tid] = c1[tid];
    if (tid < 16) sc2[tid] = c2[tid];
    if (tid < 8)  sc3[tid] = c3[tid];
    __syncthreads();

    float g[32];
#pragma unroll
    for (int i = 0; i < 32; i++) g[i] = g_pool[tid * 32 + i];

    float v1[32];
#pragma unroll
    for (int o = 0; o < 32; o++) {
        float a = sc1[o];
#pragma unroll
        for (int k = 0; k < 32; k++) a += g[k] * sA1[k * 32 + o];
        v1[o] = fmaxf(a, 0.f);
    }
    float v2[16];
#pragma unroll
    for (int o = 0; o < 16; o++) {
        float a = sc2[o];
#pragma unroll
        for (int k = 0; k < 32; k++) a += v1[k] * sA2[k * 16 + o];
        v2[o] = fmaxf(a, 0.f);
    }
    float v3[8];
#pragma unroll
    for (int o = 0; o < 8; o++) {
        float a = sc3[o];
#pragma unroll
        for (int k = 0; k < 16; k++) a += v2[k] * sA3[k * 8 + o];
        v3[o] = fmaxf(a, 0.f);
    }
    float r = __ldg(c4);
#pragma unroll
    for (int k = 0; k < 8; k++) r += v3[k] * sA4[k];
    out[tid] = r;
}

// ---------------- launch: xw1 on side stream overlaps CSR build --------------
extern "C" void kernel_launch(void* const* d_in, const int* in_sizes, int n_in,
                              void* d_out, int out_size) {
    const float* x     = (const float*)d_in[0];
    const int*   ei    = (const int*)  d_in[1];
    const int*   batch = (const int*)  d_in[2];
    const float* W1 = (const float*)d_in[3];  const float* b1 = (const float*)d_in[4];
    const float* W2 = (const float*)d_in[5];  const float* b2 = (const float*)d_in[6];
    const float* A1 = (const float*)d_in[7];  const float* c1 = (const float*)d_in[8];
    const float* A2 = (const float*)d_in[9];  const float* c2 = (const float*)d_in[10];
    const float* A3 = (const float*)d_in[11]; const float* c3 = (const float*)d_in[12];
    const float* A4 = (const float*)d_in[13]; const float* c4 = (const float*)d_in[14];
    float* out = (float*)d_out;

    // side stream + fork/join events (created once, outside capture)
    static cudaStream_t s2 = [] {
        cudaStream_t s; cudaStreamCreateWithFlags(&s, cudaStreamNonBlocking); return s;
    }();
    static cudaEvent_t evF = [] {
        cudaEvent_t e; cudaEventCreateWithFlags(&e, cudaEventDisableTiming); return e;
    }();
    static cudaEvent_t evJ = [] {
        cudaEvent_t e; cudaEventCreateWithFlags(&e, cudaEventDisableTiming); return e;
    }();

    // fork: xw1 is fully independent
    cudaEventRecord(evF, 0);
    cudaStreamWaitEvent(s2, evF, 0);
    xw1_kernel<<<(N_NODES + 127) / 128, 256, 0, s2>>>(x, W1);             // idx 0

    // main: CSR build + pool zero, overlapping xw1
    cur_init_kernel<<<(N_NODES + 255) / 256, 256>>>();                    // idx 1
    csr_fill_kernel<<<(N_EDGES + 255) / 256, 256>>>(ei);                  // idx 2
    pool_zero_kernel<<<(N_GRAPHS * 32 + 255) / 256, 256>>>();             // idx 3

    // join: scale1 touches h1 (s2) and cursor (main)
    cudaEventRecord(evJ, s2);
    cudaStreamWaitEvent(0, evJ, 0);

    scale1_kernel<<<(N_NODES * 8 + 255) / 256, 256>>>();
    gather1_xw2_kernel<<<N_NODES * 8 / 256, 256>>>(W2, b1);               // fused L1+W2
    gather2_pool_kernel<<<(N_NODES * 4 + 255) / 256, 256>>>(batch, b2);   // fused L2+pool
    mlp_kernel<<<1, 128>>>(A1, c1, A2, c2, A3, c3, A4, c4, out);
}